// round 1
// baseline (speedup 1.0000x reference)
#include <cuda_runtime.h>

// ---------------- scratch (device globals; no runtime allocation) -------------
// doff:    B=2, 144 ch, 256x256
// aligned: B=2,  64 ch, 256x256
// x1:      B=2,  64 ch, 256x256
__device__ float g_doff[2 * 144 * 256 * 256];
__device__ float g_aligned[2 * 64 * 256 * 256];
__device__ float g_x1[2 * 64 * 256 * 256];

static constexpr int Hc = 256;
static constexpr int Wc = 256;
static constexpr int HWc = Hc * Wc;

static constexpr int TS = 32;    // spatial tile (32x32 outputs)
static constexpr int HALO = 34;  // TS + 2
static constexpr int ICC = 8;    // input-channel chunk in smem
static constexpr int OCB = 8;    // output channels per block

// ---------------- generic 3x3 SAME conv, NCHW, fp32 --------------------------
// inA: first 64 input channels, inB: next 64 (for IC=128 concat case).
// Physical batch stride of every activation tensor is 64*HW.
template <int IC>
__global__ __launch_bounds__(256) void conv3x3_tiled(
    const float* __restrict__ inA, const float* __restrict__ inB,
    const float* __restrict__ w,    // [OC][IC][3][3]
    const float* __restrict__ bias, // [OC]
    float* __restrict__ out,        // [B][OC][H][W]
    int OC, int do_relu, const float* __restrict__ addsrc) {
  __shared__ float s_in[ICC * HALO * HALO];
  __shared__ float s_w[OCB][ICC][9];

  const int tilesW = Wc / TS;
  const int tx0 = (blockIdx.x % tilesW) * TS;
  const int ty0 = (blockIdx.x / tilesW) * TS;
  const int oc0 = blockIdx.y * OCB;
  const int b = blockIdx.z;
  const int t = threadIdx.x;
  const int px = (t & 15) * 2;  // 2x2 micro-tile per thread
  const int py = (t >> 4) * 2;

  float acc[OCB][4];
#pragma unroll
  for (int o = 0; o < OCB; o++) {
    acc[o][0] = 0.f; acc[o][1] = 0.f; acc[o][2] = 0.f; acc[o][3] = 0.f;
  }

  for (int ic0 = 0; ic0 < IC; ic0 += ICC) {
    // ---- load input halo chunk (zero-padded) ----
    for (int i = t; i < ICC * HALO * HALO; i += 256) {
      int ic = i / (HALO * HALO);
      int r = i - ic * (HALO * HALO);
      int yy = r / HALO;
      int xx = r - yy * HALO;
      int gy = ty0 + yy - 1;
      int gx = tx0 + xx - 1;
      float v = 0.f;
      if ((unsigned)gy < (unsigned)Hc && (unsigned)gx < (unsigned)Wc) {
        int icg = ic0 + ic;
        const float* src = inA;
        int icl = icg;
        if (IC == 128 && icg >= 64) { src = inB; icl = icg - 64; }
        v = src[(b * 64 + icl) * HWc + gy * Wc + gx];
      }
      s_in[i] = v;
    }
    // ---- load weight chunk: OCB x ICC x 9 ----
    for (int i = t; i < OCB * ICC * 9; i += 256) {
      int oc = i / (ICC * 9);
      int r = i - oc * (ICC * 9);
      s_w[oc][0][r] = w[(oc0 + oc) * IC * 9 + ic0 * 9 + r];
    }
    __syncthreads();

#pragma unroll 1
    for (int ic = 0; ic < ICC; ic++) {
      const float* sp = &s_in[ic * HALO * HALO + py * HALO + px];
#pragma unroll
      for (int ky = 0; ky < 3; ky++) {
#pragma unroll
        for (int kx = 0; kx < 3; kx++) {
          float i00 = sp[ky * HALO + kx];
          float i01 = sp[ky * HALO + kx + 1];
          float i10 = sp[(ky + 1) * HALO + kx];
          float i11 = sp[(ky + 1) * HALO + kx + 1];
#pragma unroll
          for (int o = 0; o < OCB; o++) {
            float wv = s_w[o][ic][ky * 3 + kx];
            acc[o][0] = fmaf(i00, wv, acc[o][0]);
            acc[o][1] = fmaf(i01, wv, acc[o][1]);
            acc[o][2] = fmaf(i10, wv, acc[o][2]);
            acc[o][3] = fmaf(i11, wv, acc[o][3]);
          }
        }
      }
    }
    __syncthreads();
  }

  // ---- epilogue: bias, relu, optional residual add ----
#pragma unroll
  for (int o = 0; o < OCB; o++) {
    int oc = oc0 + o;
    float bv = bias[oc];
#pragma unroll
    for (int d = 0; d < 4; d++) {
      int dy = d >> 1, dx = d & 1;
      int gy = ty0 + py + dy;
      int gx = tx0 + px + dx;
      float v = acc[o][d] + bv;
      if (do_relu) v = fmaxf(v, 0.f);
      int idx = (b * OC + oc) * HWc + gy * Wc + gx;
      if (addsrc) v += addsrc[idx];  // only used when OC==64 (same layout)
      out[idx] = v;
    }
  }
}

// ---------------- deformable conv (G=8, Cg=8, K=3) ---------------------------
// One thread per (b,g,y,x); 8 output channels accumulated in registers.
__global__ __launch_bounds__(256) void deform_kernel(
    const float* __restrict__ ref,    // [B][64][H][W]
    const float* __restrict__ doff,   // [B][144][H][W]
    const float* __restrict__ w_def,  // [64][8][3][3]
    const float* __restrict__ b_def,  // [64]
    float* __restrict__ out) {        // [B][64][H][W]
  const int x = threadIdx.x;
  const int y = blockIdx.x;
  const int g = blockIdx.y;
  const int b = blockIdx.z;

  __shared__ float s_w[8][8][9];  // [o][i][k] for this group
  for (int i = threadIdx.x; i < 576; i += 256) {
    int o = i / 72;
    int r = i - o * 72;
    s_w[o][0][r] = w_def[(g * 8 + o) * 72 + r];
  }
  __syncthreads();

  const float* refg = ref + (b * 64 + g * 8) * HWc;
  const float* offg = doff + (b * 144 + g * 18) * HWc + y * Wc + x;

  float acc[8];
#pragma unroll
  for (int o = 0; o < 8; o++) acc[o] = 0.f;

#pragma unroll 1
  for (int k = 0; k < 9; k++) {
    float dy = offg[(2 * k) * HWc];
    float dx = offg[(2 * k + 1) * HWc];
    float pyf = dy + (float)(y + k / 3 - 1);
    float pxf = dx + (float)(x + k % 3 - 1);
    float fy = floorf(pyf);
    float fx = floorf(pxf);
    int y0 = (int)fy;
    int x0 = (int)fx;
    float ly = pyf - fy;
    float lx = pxf - fx;
    float w00 = (1.f - ly) * (1.f - lx);
    float w01 = (1.f - ly) * lx;
    float w10 = ly * (1.f - lx);
    float w11 = ly * lx;
    bool vy0 = (unsigned)y0 < (unsigned)Hc;
    bool vy1 = (unsigned)(y0 + 1) < (unsigned)Hc;
    bool vx0 = (unsigned)x0 < (unsigned)Wc;
    bool vx1 = (unsigned)(x0 + 1) < (unsigned)Wc;
    if (!(vy0 && vx0)) w00 = 0.f;
    if (!(vy0 && vx1)) w01 = 0.f;
    if (!(vy1 && vx0)) w10 = 0.f;
    if (!(vy1 && vx1)) w11 = 0.f;
    int cy0 = min(max(y0, 0), Hc - 1);
    int cy1 = min(max(y0 + 1, 0), Hc - 1);
    int cx0 = min(max(x0, 0), Wc - 1);
    int cx1 = min(max(x0 + 1, 0), Wc - 1);
    int i00 = cy0 * Wc + cx0;
    int i01 = cy0 * Wc + cx1;
    int i10 = cy1 * Wc + cx0;
    int i11 = cy1 * Wc + cx1;
#pragma unroll
    for (int c = 0; c < 8; c++) {
      const float* rp = refg + c * HWc;
      float s = w00 * rp[i00] + w01 * rp[i01] + w10 * rp[i10] + w11 * rp[i11];
#pragma unroll
      for (int o = 0; o < 8; o++) acc[o] = fmaf(s, s_w[o][c][k], acc[o]);
    }
  }

#pragma unroll
  for (int o = 0; o < 8; o++)
    out[(b * 64 + g * 8 + o) * HWc + y * Wc + x] = acc[o] + b_def[g * 8 + o];
}

// ---------------- launch ------------------------------------------------------
extern "C" void kernel_launch(void* const* d_in, const int* in_sizes, int n_in,
                              void* d_out, int out_size) {
  const float* offset = (const float*)d_in[0];
  const float* ref    = (const float*)d_in[1];
  const float* w_off  = (const float*)d_in[2];
  const float* b_off  = (const float*)d_in[3];
  const float* w_def  = (const float*)d_in[4];
  const float* b_def  = (const float*)d_in[5];
  const float* w_r1   = (const float*)d_in[6];
  const float* b_r1   = (const float*)d_in[7];
  const float* w_r2   = (const float*)d_in[8];
  const float* b_r2   = (const float*)d_in[9];
  float* out = (float*)d_out;

  float *p_doff, *p_aligned, *p_x1;
  cudaGetSymbolAddress((void**)&p_doff, g_doff);
  cudaGetSymbolAddress((void**)&p_aligned, g_aligned);
  cudaGetSymbolAddress((void**)&p_x1, g_x1);

  const int tiles = (Hc / TS) * (Wc / TS);  // 64

  // 1) deform_offsets = conv3x3(offset, w_off, b_off)   64 -> 144
  {
    dim3 grid(tiles, 144 / OCB, 2);
    conv3x3_tiled<64><<<grid, 256>>>(offset, nullptr, w_off, b_off, p_doff,
                                     144, 0, nullptr);
  }
  // 2) aligned_ref = deform_conv2d(ref, deform_offsets, w_def, b_def)
  {
    dim3 grid(Hc, 8, 2);
    deform_kernel<<<grid, 256>>>(ref, p_doff, w_def, b_def, p_aligned);
  }
  // 3) x1 = relu(conv3x3(concat(ref, aligned), w_r1, b_r1))  128 -> 64
  {
    dim3 grid(tiles, 64 / OCB, 2);
    conv3x3_tiled<128><<<grid, 256>>>(ref, p_aligned, w_r1, b_r1, p_x1,
                                      64, 1, nullptr);
  }
  // 4) out = relu(conv3x3(x1, w_r2, b_r2)) + aligned        64 -> 64
  {
    dim3 grid(tiles, 64 / OCB, 2);
    conv3x3_tiled<64><<<grid, 256>>>(p_x1, nullptr, w_r2, b_r2, out,
                                     64, 1, p_aligned);
  }
}

// round 2
// speedup vs baseline: 1.0802x; 1.0802x over previous
#include <cuda_runtime.h>

// ---------------- scratch (device globals; no runtime allocation) -------------
__device__ float g_doff[2 * 144 * 256 * 256];
__device__ float g_aligned[2 * 64 * 256 * 256];
__device__ float g_x1[2 * 64 * 256 * 256];

static constexpr int Hc = 256;
static constexpr int Wc = 256;
static constexpr int HWc = Hc * Wc;

static constexpr int TS = 32;     // spatial tile (32x32 outputs)
static constexpr int HALO = 34;   // TS + 2
static constexpr int HPAD = 36;   // padded row stride (alignment for float4)
static constexpr int ICC = 8;     // input-channel chunk in smem
static constexpr int OCB = 8;     // output channels per block

// ---------------- generic 3x3 SAME conv, NCHW, fp32 --------------------------
// Thread layout: 256 threads = 32 rows x 8 col-groups; each thread computes a
// 1x4 horizontal strip of outputs for 8 output channels (32 accumulators).
// Input loads: 2 vector LDS per (ic, row) — conflict-free.
// Weight loads: s_w[ic][tap][o] layout -> 2 broadcast LDS.128 per (ic, tap).
template <int IC>
__global__ __launch_bounds__(256, 2) void conv3x3_tiled(
    const float* __restrict__ inA, const float* __restrict__ inB,
    const float* __restrict__ w,    // [OC][IC][3][3]
    const float* __restrict__ bias, // [OC]
    float* __restrict__ out,        // [B][OC][H][W]
    int OC, int do_relu, const float* __restrict__ addsrc) {
  __shared__ float s_in[ICC][HALO][HPAD];
  __shared__ float s_w[ICC][9][OCB];

  const int tilesW = Wc / TS;
  const int tx0 = (blockIdx.x % tilesW) * TS;
  const int ty0 = (blockIdx.x / tilesW) * TS;
  const int oc0 = blockIdx.y * OCB;
  const int b = blockIdx.z;
  const int t = threadIdx.x;
  const int px = (t & 7) * 4;  // 1x4 strip
  const int py = t >> 3;       // 0..31

  float acc[OCB][4];
#pragma unroll
  for (int o = 0; o < OCB; o++) {
    acc[o][0] = 0.f; acc[o][1] = 0.f; acc[o][2] = 0.f; acc[o][3] = 0.f;
  }

  for (int ic0 = 0; ic0 < IC; ic0 += ICC) {
    // ---- load input halo chunk (zero-padded; pad cols 34,35 are dead) ----
    for (int i = t; i < ICC * HALO * HPAD; i += 256) {
      int ic = i / (HALO * HPAD);
      int r = i - ic * (HALO * HPAD);
      int yy = r / HPAD;
      int xx = r - yy * HPAD;
      int gy = ty0 + yy - 1;
      int gx = tx0 + xx - 1;
      float v = 0.f;
      if ((unsigned)gy < (unsigned)Hc && (unsigned)gx < (unsigned)Wc) {
        int icg = ic0 + ic;
        const float* src = inA;
        int icl = icg;
        if (IC == 128 && icg >= 64) { src = inB; icl = icg - 64; }
        v = src[(b * 64 + icl) * HWc + gy * Wc + gx];
      }
      (&s_in[0][0][0])[i] = v;
    }
    // ---- load weight chunk, transposed: [ic][tap][o] ----
    for (int i = t; i < ICC * 9 * OCB; i += 256) {
      int ic = i / (9 * OCB);
      int r = i - ic * (9 * OCB);
      int k = r >> 3;
      int o = r & 7;
      s_w[ic][k][o] = w[(oc0 + o) * IC * 9 + (ic0 + ic) * 9 + k];
    }
    __syncthreads();

#pragma unroll 1
    for (int ic = 0; ic < ICC; ic++) {
#pragma unroll
      for (int ky = 0; ky < 3; ky++) {
        const float* rowp = &s_in[ic][py + ky][px];
        float4 va = *(const float4*)rowp;        // cols px..px+3
        float2 vb = *(const float2*)(rowp + 4);  // cols px+4..px+5
        float rr[6];
        rr[0] = va.x; rr[1] = va.y; rr[2] = va.z; rr[3] = va.w;
        rr[4] = vb.x; rr[5] = vb.y;
#pragma unroll
        for (int kx = 0; kx < 3; kx++) {
          float4 wA = *(const float4*)&s_w[ic][ky * 3 + kx][0];
          float4 wB = *(const float4*)&s_w[ic][ky * 3 + kx][4];
          float w8[8] = {wA.x, wA.y, wA.z, wA.w, wB.x, wB.y, wB.z, wB.w};
#pragma unroll
          for (int o = 0; o < 8; o++) {
#pragma unroll
            for (int j = 0; j < 4; j++)
              acc[o][j] = fmaf(rr[kx + j], w8[o], acc[o][j]);
          }
        }
      }
    }
    __syncthreads();
  }

  // ---- epilogue: bias, relu, optional residual add; vectorized stores ----
  const int gy = ty0 + py;
  const int gx = tx0 + px;
#pragma unroll
  for (int o = 0; o < OCB; o++) {
    int oc = oc0 + o;
    float bv = bias[oc];
    float4 v;
    v.x = acc[o][0] + bv;
    v.y = acc[o][1] + bv;
    v.z = acc[o][2] + bv;
    v.w = acc[o][3] + bv;
    if (do_relu) {
      v.x = fmaxf(v.x, 0.f); v.y = fmaxf(v.y, 0.f);
      v.z = fmaxf(v.z, 0.f); v.w = fmaxf(v.w, 0.f);
    }
    int idx = (b * OC + oc) * HWc + gy * Wc + gx;
    if (addsrc) {
      float4 a4 = *(const float4*)&addsrc[idx];
      v.x += a4.x; v.y += a4.y; v.z += a4.z; v.w += a4.w;
    }
    *(float4*)&out[idx] = v;
  }
}

// ---------------- deformable conv (G=8, Cg=8, K=3) ---------------------------
__global__ __launch_bounds__(256) void deform_kernel(
    const float* __restrict__ ref,    // [B][64][H][W]
    const float* __restrict__ doff,   // [B][144][H][W]
    const float* __restrict__ w_def,  // [64][8][3][3]
    const float* __restrict__ b_def,  // [64]
    float* __restrict__ out) {        // [B][64][H][W]
  const int x = threadIdx.x;
  const int y = blockIdx.x;
  const int g = blockIdx.y;
  const int b = blockIdx.z;

  __shared__ float s_w[8][8][9];  // [o][i][k] for this group
  for (int i = threadIdx.x; i < 576; i += 256) {
    int o = i / 72;
    int r = i - o * 72;
    s_w[o][0][r] = w_def[(g * 8 + o) * 72 + r];
  }
  __syncthreads();

  const float* refg = ref + (b * 64 + g * 8) * HWc;
  const float* offg = doff + (b * 144 + g * 18) * HWc + y * Wc + x;

  float acc[8];
#pragma unroll
  for (int o = 0; o < 8; o++) acc[o] = 0.f;

#pragma unroll 1
  for (int k = 0; k < 9; k++) {
    float dy = offg[(2 * k) * HWc];
    float dx = offg[(2 * k + 1) * HWc];
    float pyf = dy + (float)(y + k / 3 - 1);
    float pxf = dx + (float)(x + k % 3 - 1);
    float fy = floorf(pyf);
    float fx = floorf(pxf);
    int y0 = (int)fy;
    int x0 = (int)fx;
    float ly = pyf - fy;
    float lx = pxf - fx;
    float w00 = (1.f - ly) * (1.f - lx);
    float w01 = (1.f - ly) * lx;
    float w10 = ly * (1.f - lx);
    float w11 = ly * lx;
    bool vy0 = (unsigned)y0 < (unsigned)Hc;
    bool vy1 = (unsigned)(y0 + 1) < (unsigned)Hc;
    bool vx0 = (unsigned)x0 < (unsigned)Wc;
    bool vx1 = (unsigned)(x0 + 1) < (unsigned)Wc;
    if (!(vy0 && vx0)) w00 = 0.f;
    if (!(vy0 && vx1)) w01 = 0.f;
    if (!(vy1 && vx0)) w10 = 0.f;
    if (!(vy1 && vx1)) w11 = 0.f;
    int cy0 = min(max(y0, 0), Hc - 1);
    int cy1 = min(max(y0 + 1, 0), Hc - 1);
    int cx0 = min(max(x0, 0), Wc - 1);
    int cx1 = min(max(x0 + 1, 0), Wc - 1);
    int i00 = cy0 * Wc + cx0;
    int i01 = cy0 * Wc + cx1;
    int i10 = cy1 * Wc + cx0;
    int i11 = cy1 * Wc + cx1;
#pragma unroll
    for (int c = 0; c < 8; c++) {
      const float* rp = refg + c * HWc;
      float s = w00 * rp[i00] + w01 * rp[i01] + w10 * rp[i10] + w11 * rp[i11];
#pragma unroll
      for (int o = 0; o < 8; o++) acc[o] = fmaf(s, s_w[o][c][k], acc[o]);
    }
  }

#pragma unroll
  for (int o = 0; o < 8; o++)
    out[(b * 64 + g * 8 + o) * HWc + y * Wc + x] = acc[o] + b_def[g * 8 + o];
}

// ---------------- launch ------------------------------------------------------
extern "C" void kernel_launch(void* const* d_in, const int* in_sizes, int n_in,
                              void* d_out, int out_size) {
  const float* offset = (const float*)d_in[0];
  const float* ref    = (const float*)d_in[1];
  const float* w_off  = (const float*)d_in[2];
  const float* b_off  = (const float*)d_in[3];
  const float* w_def  = (const float*)d_in[4];
  const float* b_def  = (const float*)d_in[5];
  const float* w_r1   = (const float*)d_in[6];
  const float* b_r1   = (const float*)d_in[7];
  const float* w_r2   = (const float*)d_in[8];
  const float* b_r2   = (const float*)d_in[9];
  float* out = (float*)d_out;

  float *p_doff, *p_aligned, *p_x1;
  cudaGetSymbolAddress((void**)&p_doff, g_doff);
  cudaGetSymbolAddress((void**)&p_aligned, g_aligned);
  cudaGetSymbolAddress((void**)&p_x1, g_x1);

  const int tiles = (Hc / TS) * (Wc / TS);  // 64

  // 1) deform_offsets = conv3x3(offset, w_off, b_off)   64 -> 144
  {
    dim3 grid(tiles, 144 / OCB, 2);
    conv3x3_tiled<64><<<grid, 256>>>(offset, nullptr, w_off, b_off, p_doff,
                                     144, 0, nullptr);
  }
  // 2) aligned_ref = deform_conv2d(ref, deform_offsets, w_def, b_def)
  {
    dim3 grid(Hc, 8, 2);
    deform_kernel<<<grid, 256>>>(ref, p_doff, w_def, b_def, p_aligned);
  }
  // 3) x1 = relu(conv3x3(concat(ref, aligned), w_r1, b_r1))  128 -> 64
  {
    dim3 grid(tiles, 64 / OCB, 2);
    conv3x3_tiled<128><<<grid, 256>>>(ref, p_aligned, w_r1, b_r1, p_x1,
                                      64, 1, nullptr);
  }
  // 4) out = relu(conv3x3(x1, w_r2, b_r2)) + aligned        64 -> 64
  {
    dim3 grid(tiles, 64 / OCB, 2);
    conv3x3_tiled<64><<<grid, 256>>>(p_x1, nullptr, w_r2, b_r2, out,
                                     64, 1, p_aligned);
  }
}